// round 1
// baseline (speedup 1.0000x reference)
#include <cuda_runtime.h>
#include <cstddef>

#define N_NODES 100000
#define F_DIM   256
#define NNZ     1600000
#define NF4     (N_NODES * (F_DIM / 4))   // 6,400,000 float4

// ---------------- scratch (no allocation allowed) ----------------
__device__ float g_xt[(size_t)N_NODES * F_DIM];  // GEMM output (both layers)
__device__ float g_m [(size_t)N_NODES * F_DIM];  // hyperedge accumulator
__device__ float g_h [(size_t)N_NODES * F_DIM];  // layer-1 hidden
__device__ float g_Dinv[N_NODES];
__device__ float g_Binv[N_NODES];

// ---------------- helpers ----------------
__device__ __forceinline__ void red4(float* p, float4 v) {
    asm volatile("red.global.add.v4.f32 [%0], {%1,%2,%3,%4};"
                 :: "l"(__cvta_generic_to_global(p)),
                    "f"(v.x), "f"(v.y), "f"(v.z), "f"(v.w)
                 : "memory");
}

// ---------------- degree kernels ----------------
__global__ void k_zero_deg() {
    int i = blockIdx.x * blockDim.x + threadIdx.x;
    if (i < N_NODES) { g_Dinv[i] = 0.f; g_Binv[i] = 0.f; }
}

__global__ void k_deg(const int* __restrict__ ei) {
    int i = blockIdx.x * blockDim.x + threadIdx.x;
    if (i < NNZ) {
        atomicAdd(&g_Dinv[ei[i]], 1.0f);
        atomicAdd(&g_Binv[ei[i + NNZ]], 1.0f);
    }
}

__global__ void k_inv() {
    int i = blockIdx.x * blockDim.x + threadIdx.x;
    if (i < N_NODES) {
        float d = g_Dinv[i]; g_Dinv[i] = (d > 0.f) ? 1.f / d : 0.f;
        float b = g_Binv[i]; g_Binv[i] = (b > 0.f) ? 1.f / b : 0.f;
    }
}

// ---------------- zero kernels ----------------
__global__ void k_zero_m() {
    int i = blockIdx.x * blockDim.x + threadIdx.x;
    if (i < NF4) ((float4*)g_m)[i] = make_float4(0.f, 0.f, 0.f, 0.f);
}
__global__ void k_zero_h() {
    int i = blockIdx.x * blockDim.x + threadIdx.x;
    if (i < NF4) ((float4*)g_h)[i] = make_float4(0.f, 0.f, 0.f, 0.f);
}
__global__ void k_zero_ext(float* __restrict__ p) {
    int i = blockIdx.x * blockDim.x + threadIdx.x;
    if (i < NF4) ((float4*)p)[i] = make_float4(0.f, 0.f, 0.f, 0.f);
}

// ---------------- fp32 SGEMM: C(g_xt) = A[N,256] @ W[256,256] ----------------
#define BM 128
#define BN 64
#define BK 16
#define TM 8
#define TN 4

__global__ __launch_bounds__(256)
void k_gemm(const float* __restrict__ A_ext, const float* __restrict__ W, int use_h) {
    __shared__ float As[BK][BM];
    __shared__ float Bs[BK][BN];
    const float* __restrict__ A = use_h ? g_h : A_ext;
    float* __restrict__ C = g_xt;

    int bm = blockIdx.y * BM;
    int bn = blockIdx.x * BN;
    int tid = threadIdx.x;
    int tx = tid & 15;   // 0..15 column group (TN=4 each)
    int ty = tid >> 4;   // 0..15 row group    (TM=8 each)

    float acc[TM][TN];
    #pragma unroll
    for (int i = 0; i < TM; ++i)
        #pragma unroll
        for (int j = 0; j < TN; ++j) acc[i][j] = 0.f;

    for (int k0 = 0; k0 < F_DIM; k0 += BK) {
        // load A tile (128x16) transposed: 512 float4, 2 per thread
        #pragma unroll
        for (int l = 0; l < 2; ++l) {
            int idx = tid + l * 256;
            int r  = idx >> 2;
            int c4 = (idx & 3) << 2;
            int grow = bm + r;
            float4 v = make_float4(0.f, 0.f, 0.f, 0.f);
            if (grow < N_NODES)
                v = *(const float4*)(A + (size_t)grow * F_DIM + k0 + c4);
            As[c4 + 0][r] = v.x; As[c4 + 1][r] = v.y;
            As[c4 + 2][r] = v.z; As[c4 + 3][r] = v.w;
        }
        // load B tile (16x64): 256 float4, 1 per thread
        {
            int r  = tid >> 4;
            int c4 = (tid & 15) << 2;
            float4 v = *(const float4*)(W + (size_t)(k0 + r) * F_DIM + bn + c4);
            *(float4*)&Bs[r][c4] = v;
        }
        __syncthreads();

        #pragma unroll
        for (int kk = 0; kk < BK; ++kk) {
            float a[TM], b[TN];
            #pragma unroll
            for (int i = 0; i < TM; ++i) a[i] = As[kk][ty * TM + i];
            #pragma unroll
            for (int j = 0; j < TN; ++j) b[j] = Bs[kk][tx * TN + j];
            #pragma unroll
            for (int i = 0; i < TM; ++i)
                #pragma unroll
                for (int j = 0; j < TN; ++j)
                    acc[i][j] = fmaf(a[i], b[j], acc[i][j]);
        }
        __syncthreads();
    }

    #pragma unroll
    for (int i = 0; i < TM; ++i) {
        int grow = bm + ty * TM + i;
        if (grow < N_NODES) {
            float4 v = make_float4(acc[i][0], acc[i][1], acc[i][2], acc[i][3]);
            *(float4*)(C + (size_t)grow * F_DIM + bn + tx * TN) = v;
        }
    }
}

// ---------------- scatter: node -> hyperedge  (g_m[dst] += g_xt[src]) --------
__global__ __launch_bounds__(256)
void k_scatter_n2e(const int* __restrict__ ei) {
    int w = (blockIdx.x * blockDim.x + threadIdx.x) >> 5;
    if (w >= NNZ) return;
    int lane = threadIdx.x & 31;
    int s = __ldg(ei + w);
    int d = __ldg(ei + NNZ + w);
    const float4* xr = (const float4*)(g_xt + (size_t)s * F_DIM);
    float4*       mr = (float4*)(g_m  + (size_t)d * F_DIM);
    red4((float*)(mr + lane),      __ldg(xr + lane));
    red4((float*)(mr + lane + 32), __ldg(xr + lane + 32));
}

// ------- scatter: hyperedge -> node  (dst_buf[src] += g_m[dst]*Binv[dst]) ----
__global__ __launch_bounds__(256)
void k_scatter_e2n(const int* __restrict__ ei, float* __restrict__ dout, int to_out) {
    int w = (blockIdx.x * blockDim.x + threadIdx.x) >> 5;
    if (w >= NNZ) return;
    int lane = threadIdx.x & 31;
    int s = __ldg(ei + w);
    int d = __ldg(ei + NNZ + w);
    float binv = __ldg(&g_Binv[d]);
    const float4* mr = (const float4*)(g_m + (size_t)d * F_DIM);
    float* tgt = (to_out ? dout : g_h) + (size_t)s * F_DIM;
    float4 v0 = __ldg(mr + lane);
    float4 v1 = __ldg(mr + lane + 32);
    v0.x *= binv; v0.y *= binv; v0.z *= binv; v0.w *= binv;
    v1.x *= binv; v1.y *= binv; v1.z *= binv; v1.w *= binv;
    red4(tgt + lane * 4,        v0);
    red4(tgt + (lane + 32) * 4, v1);
}

// ---------------- epilogues ----------------
__device__ __forceinline__ float prelu(float v, float a) {
    return v >= 0.f ? v : a * v;
}

// g_h = prelu(g_h * Dinv + b1)
__global__ __launch_bounds__(256)
void k_ew1(const float* __restrict__ b, const float* __restrict__ a) {
    int i = blockIdx.x * blockDim.x + threadIdx.x;
    if (i >= NF4) return;
    int row = i >> 6;
    int c   = (i & 63) << 2;
    float dinv = g_Dinv[row];
    float av = __ldg(a);
    float4 v  = ((const float4*)g_h)[i];
    float4 bb = *(const float4*)(b + c);
    v.x = prelu(fmaf(v.x, dinv, bb.x), av);
    v.y = prelu(fmaf(v.y, dinv, bb.y), av);
    v.z = prelu(fmaf(v.z, dinv, bb.z), av);
    v.w = prelu(fmaf(v.w, dinv, bb.w), av);
    ((float4*)g_h)[i] = v;
}

// out = prelu(out * Dinv + b2 + x)
__global__ __launch_bounds__(256)
void k_ew2(float* __restrict__ o, const float* __restrict__ x,
           const float* __restrict__ b, const float* __restrict__ a) {
    int i = blockIdx.x * blockDim.x + threadIdx.x;
    if (i >= NF4) return;
    int row = i >> 6;
    int c   = (i & 63) << 2;
    float dinv = g_Dinv[row];
    float av = __ldg(a);
    float4 v  = ((float4*)o)[i];
    float4 xx = ((const float4*)x)[i];
    float4 bb = *(const float4*)(b + c);
    v.x = prelu(fmaf(v.x, dinv, bb.x) + xx.x, av);
    v.y = prelu(fmaf(v.y, dinv, bb.y) + xx.y, av);
    v.z = prelu(fmaf(v.z, dinv, bb.z) + xx.z, av);
    v.w = prelu(fmaf(v.w, dinv, bb.w) + xx.w, av);
    ((float4*)o)[i] = v;
}

// ---------------- launch ----------------
extern "C" void kernel_launch(void* const* d_in, const int* in_sizes, int n_in,
                              void* d_out, int out_size) {
    const float* x  = (const float*)d_in[0];
    const int*   ei = (const int*)  d_in[1];
    const float* W1 = (const float*)d_in[2];
    const float* b1 = (const float*)d_in[3];
    const float* W2 = (const float*)d_in[4];
    const float* b2 = (const float*)d_in[5];
    const float* a  = (const float*)d_in[6];
    float* out = (float*)d_out;

    const int ZB = (NF4 + 255) / 256;            // 25000
    const int SB = (NNZ * 32 + 255) / 256;       // 200000 blocks (warp per edge)
    dim3 ggrid(F_DIM / BN, (N_NODES + BM - 1) / BM);

    // degrees (shared by both layers)
    k_zero_deg<<<(N_NODES + 255) / 256, 256>>>();
    k_deg<<<(NNZ + 255) / 256, 256>>>(ei);
    k_inv<<<(N_NODES + 255) / 256, 256>>>();

    // ---- layer 1 ----
    k_gemm<<<ggrid, 256>>>(x, W1, 0);
    k_zero_m<<<ZB, 256>>>();
    k_scatter_n2e<<<SB, 256>>>(ei);
    k_zero_h<<<ZB, 256>>>();
    k_scatter_e2n<<<SB, 256>>>(ei, out, 0);
    k_ew1<<<ZB, 256>>>(b1, a);

    // ---- layer 2 ----
    k_gemm<<<ggrid, 256>>>(x /*unused*/, W2, 1);
    k_zero_m<<<ZB, 256>>>();
    k_scatter_n2e<<<SB, 256>>>(ei);
    k_zero_ext<<<ZB, 256>>>(out);
    k_scatter_e2n<<<SB, 256>>>(ei, out, 1);
    k_ew2<<<ZB, 256>>>(out, x, b2, a);
}

// round 3
// speedup vs baseline: 2.0177x; 2.0177x over previous
#include <cuda_runtime.h>
#include <cstddef>

#define N_NODES 100000
#define F_DIM   256
#define NNZ     1600000
#define NB1     98          // ceil(N_NODES/1024)

// ---------------- scratch (no allocation allowed) ----------------
// NOTE: __device__ symbols are ONLY referenced from device code, never passed
// as kernel arguments from host (host would pass the shadow-symbol address).
__device__ float g_xt[(size_t)N_NODES * F_DIM];  // GEMM output (both layers)
__device__ float g_m [(size_t)N_NODES * F_DIM];  // hyperedge accumulator
__device__ float g_h [(size_t)N_NODES * F_DIM];  // layer-1 hidden

__device__ int g_degD[N_NODES];   // node out-degree (src occurrences)
__device__ int g_degB[N_NODES];   // hyperedge degree (dst occurrences)
__device__ int g_offD[N_NODES];
__device__ int g_offB[N_NODES];
__device__ int g_curD[N_NODES];
__device__ int g_curB[N_NODES];
__device__ int g_adjD[NNZ];       // grouped by src: stores dst ids
__device__ int g_adjB[NNZ];       // grouped by dst: stores src ids
__device__ int g_bsumD[NB1];
__device__ int g_bsumB[NB1];

// ---------------- CSR build ----------------
__global__ void k_zero_counts() {
    int i = blockIdx.x * blockDim.x + threadIdx.x;
    if (i < N_NODES) { g_degD[i] = 0; g_degB[i] = 0; }
}

__global__ void k_count(const int* __restrict__ ei) {
    int i = blockIdx.x * blockDim.x + threadIdx.x;
    if (i < NNZ) {
        atomicAdd(&g_degD[ei[i]], 1);
        atomicAdd(&g_degB[ei[i + NNZ]], 1);
    }
}

// per-block exclusive scan of 1024 elems; block total -> bsums
// which==0 -> D arrays, which==1 -> B arrays (selected in device code)
__global__ void k_scan1(int which) {
    const int* __restrict__ in  = which ? g_degB  : g_degD;
    int* __restrict__ out       = which ? g_offB  : g_offD;
    int* __restrict__ bsums     = which ? g_bsumB : g_bsumD;
    __shared__ int sh[1024];
    int g = blockIdx.x * 1024 + threadIdx.x;
    int v = (g < N_NODES) ? in[g] : 0;
    sh[threadIdx.x] = v;
    __syncthreads();
    #pragma unroll
    for (int off = 1; off < 1024; off <<= 1) {
        int t = (threadIdx.x >= off) ? sh[threadIdx.x - off] : 0;
        __syncthreads();
        sh[threadIdx.x] += t;
        __syncthreads();
    }
    if (g < N_NODES) out[g] = sh[threadIdx.x] - v;   // exclusive
    if (threadIdx.x == 1023) bsums[blockIdx.x] = sh[1023];
}

// single-block exclusive scan of NB1 block sums
__global__ void k_scan2(int which) {
    int* __restrict__ bsums = which ? g_bsumB : g_bsumD;
    __shared__ int sh[128];
    int v = (threadIdx.x < NB1) ? bsums[threadIdx.x] : 0;
    sh[threadIdx.x] = v;
    __syncthreads();
    #pragma unroll
    for (int off = 1; off < 128; off <<= 1) {
        int t = (threadIdx.x >= off) ? sh[threadIdx.x - off] : 0;
        __syncthreads();
        sh[threadIdx.x] += t;
        __syncthreads();
    }
    if (threadIdx.x < NB1) bsums[threadIdx.x] = sh[threadIdx.x] - v;
}

// add block offsets; also init cursors
__global__ void k_scan3(int which) {
    int* __restrict__ out         = which ? g_offB  : g_offD;
    const int* __restrict__ bsums = which ? g_bsumB : g_bsumD;
    int* __restrict__ cur         = which ? g_curB  : g_curD;
    int g = blockIdx.x * 1024 + threadIdx.x;
    if (g < N_NODES) {
        int v = out[g] + bsums[blockIdx.x];
        out[g] = v;
        cur[g] = v;
    }
}

__global__ void k_fill(const int* __restrict__ ei) {
    int i = blockIdx.x * blockDim.x + threadIdx.x;
    if (i < NNZ) {
        int s = ei[i], d = ei[i + NNZ];
        g_adjD[atomicAdd(&g_curD[s], 1)] = d;
        g_adjB[atomicAdd(&g_curB[d], 1)] = s;
    }
}

// ---------------- fp32 SGEMM: g_xt = A[N,256] @ W[256,256] ----------------
#define GBM 128
#define GBN 128
#define GBK 16

__global__ __launch_bounds__(256)
void k_gemm(const float* __restrict__ A_ext, const float* __restrict__ W, int use_h) {
    __shared__ float As[GBK][GBM];
    __shared__ float Bs[GBK][GBN];
    const float* __restrict__ A = use_h ? g_h : A_ext;   // device-side select
    float* __restrict__ C = g_xt;

    int bm = blockIdx.y * GBM;
    int bn = blockIdx.x * GBN;
    int tid = threadIdx.x;
    int tx = tid & 15;    // 0..15 -> 8 cols each
    int ty = tid >> 4;    // 0..15 -> 8 rows each

    float acc[8][8];
    #pragma unroll
    for (int i = 0; i < 8; ++i)
        #pragma unroll
        for (int j = 0; j < 8; ++j) acc[i][j] = 0.f;

    for (int k0 = 0; k0 < F_DIM; k0 += GBK) {
        // A tile 128x16 -> As[k][m]: 512 float4, 2 per thread
        #pragma unroll
        for (int l = 0; l < 2; ++l) {
            int idx = tid + l * 256;
            int r  = idx >> 2;           // 0..127
            int c4 = (idx & 3) << 2;     // 0,4,8,12
            int grow = bm + r;
            float4 v = make_float4(0.f, 0.f, 0.f, 0.f);
            if (grow < N_NODES)
                v = *(const float4*)(A + (size_t)grow * F_DIM + k0 + c4);
            As[c4 + 0][r] = v.x; As[c4 + 1][r] = v.y;
            As[c4 + 2][r] = v.z; As[c4 + 3][r] = v.w;
        }
        // B tile 16x128 -> Bs[k][n]: 512 float4, 2 per thread
        #pragma unroll
        for (int l = 0; l < 2; ++l) {
            int idx = tid + l * 256;
            int r  = idx >> 5;           // 0..15
            int c4 = (idx & 31) << 2;    // 0..124
            *(float4*)&Bs[r][c4] =
                *(const float4*)(W + (size_t)(k0 + r) * F_DIM + bn + c4);
        }
        __syncthreads();

        #pragma unroll
        for (int kk = 0; kk < GBK; ++kk) {
            float4 a0 = *(const float4*)&As[kk][ty * 8];
            float4 a1 = *(const float4*)&As[kk][ty * 8 + 4];
            float4 b0 = *(const float4*)&Bs[kk][tx * 8];
            float4 b1 = *(const float4*)&Bs[kk][tx * 8 + 4];
            float av[8] = {a0.x, a0.y, a0.z, a0.w, a1.x, a1.y, a1.z, a1.w};
            float bv[8] = {b0.x, b0.y, b0.z, b0.w, b1.x, b1.y, b1.z, b1.w};
            #pragma unroll
            for (int i = 0; i < 8; ++i)
                #pragma unroll
                for (int j = 0; j < 8; ++j)
                    acc[i][j] = fmaf(av[i], bv[j], acc[i][j]);
        }
        __syncthreads();
    }

    #pragma unroll
    for (int i = 0; i < 8; ++i) {
        int grow = bm + ty * 8 + i;
        if (grow < N_NODES) {
            float* crow = C + (size_t)grow * F_DIM + bn + tx * 8;
            *(float4*)crow       = make_float4(acc[i][0], acc[i][1], acc[i][2], acc[i][3]);
            *(float4*)(crow + 4) = make_float4(acc[i][4], acc[i][5], acc[i][6], acc[i][7]);
        }
    }
}

// ------- gather node -> hyperedge: g_m[e] = Binv[e] * sum_{src in e} g_xt[src]
__global__ __launch_bounds__(256)
void k_gather_n2e() {
    int w = (blockIdx.x * blockDim.x + threadIdx.x) >> 5;
    if (w >= N_NODES) return;
    int lane = threadIdx.x & 31;
    int off = g_offB[w];
    int deg = g_degB[w];
    const int* __restrict__ adj = g_adjB + off;

    float4 a0 = make_float4(0.f, 0.f, 0.f, 0.f);
    float4 a1 = make_float4(0.f, 0.f, 0.f, 0.f);
    #pragma unroll 2
    for (int j = 0; j < deg; ++j) {
        int s = __ldg(adj + j);
        const float4* r = (const float4*)(g_xt + (size_t)s * F_DIM);
        float4 v0 = __ldg(r + lane);
        float4 v1 = __ldg(r + lane + 32);
        a0.x += v0.x; a0.y += v0.y; a0.z += v0.z; a0.w += v0.w;
        a1.x += v1.x; a1.y += v1.y; a1.z += v1.z; a1.w += v1.w;
    }
    float binv = deg > 0 ? 1.f / (float)deg : 0.f;
    a0.x *= binv; a0.y *= binv; a0.z *= binv; a0.w *= binv;
    a1.x *= binv; a1.y *= binv; a1.z *= binv; a1.w *= binv;
    float4* mr = (float4*)(g_m + (size_t)w * F_DIM);
    mr[lane]      = a0;
    mr[lane + 32] = a1;
}

__device__ __forceinline__ float prelu(float v, float a) {
    return v >= 0.f ? v : a * v;
}

// ------- gather hyperedge -> node, fused epilogue:
// dst[i] = prelu( Dinv[i]*sum_{e ni i} g_m[e] + bias (+ xres[i]) , a )
// use_out: 1 -> write harness out pointer; 0 -> write g_h (selected device-side)
__global__ __launch_bounds__(256)
void k_gather_e2n(float* __restrict__ dout, const float* __restrict__ bias,
                  const float* __restrict__ aP, const float* __restrict__ xres,
                  int use_out, int addres) {
    int w = (blockIdx.x * blockDim.x + threadIdx.x) >> 5;
    if (w >= N_NODES) return;
    int lane = threadIdx.x & 31;
    int off = g_offD[w];
    int deg = g_degD[w];
    const int* __restrict__ adj = g_adjD + off;

    float4 a0 = make_float4(0.f, 0.f, 0.f, 0.f);
    float4 a1 = make_float4(0.f, 0.f, 0.f, 0.f);
    #pragma unroll 2
    for (int j = 0; j < deg; ++j) {
        int e = __ldg(adj + j);
        const float4* r = (const float4*)(g_m + (size_t)e * F_DIM);
        float4 v0 = __ldg(r + lane);
        float4 v1 = __ldg(r + lane + 32);
        a0.x += v0.x; a0.y += v0.y; a0.z += v0.z; a0.w += v0.w;
        a1.x += v1.x; a1.y += v1.y; a1.z += v1.z; a1.w += v1.w;
    }
    float dinv = deg > 0 ? 1.f / (float)deg : 0.f;
    float av = __ldg(aP);
    float4 bb0 = *(const float4*)(bias + lane * 4);
    float4 bb1 = *(const float4*)(bias + 128 + lane * 4);

    float4 r0, r1;
    r0.x = fmaf(a0.x, dinv, bb0.x); r0.y = fmaf(a0.y, dinv, bb0.y);
    r0.z = fmaf(a0.z, dinv, bb0.z); r0.w = fmaf(a0.w, dinv, bb0.w);
    r1.x = fmaf(a1.x, dinv, bb1.x); r1.y = fmaf(a1.y, dinv, bb1.y);
    r1.z = fmaf(a1.z, dinv, bb1.z); r1.w = fmaf(a1.w, dinv, bb1.w);

    if (addres) {
        const float4* xr = (const float4*)(xres + (size_t)w * F_DIM);
        float4 x0 = __ldg(xr + lane), x1 = __ldg(xr + lane + 32);
        r0.x += x0.x; r0.y += x0.y; r0.z += x0.z; r0.w += x0.w;
        r1.x += x1.x; r1.y += x1.y; r1.z += x1.z; r1.w += x1.w;
    }

    r0.x = prelu(r0.x, av); r0.y = prelu(r0.y, av);
    r0.z = prelu(r0.z, av); r0.w = prelu(r0.w, av);
    r1.x = prelu(r1.x, av); r1.y = prelu(r1.y, av);
    r1.z = prelu(r1.z, av); r1.w = prelu(r1.w, av);

    float* dstp = use_out ? dout : g_h;   // device-side select
    float4* dr = (float4*)(dstp + (size_t)w * F_DIM);
    dr[lane]      = r0;
    dr[lane + 32] = r1;
}

// ---------------- launch ----------------
extern "C" void kernel_launch(void* const* d_in, const int* in_sizes, int n_in,
                              void* d_out, int out_size) {
    const float* x  = (const float*)d_in[0];
    const int*   ei = (const int*)  d_in[1];
    const float* W1 = (const float*)d_in[2];
    const float* b1 = (const float*)d_in[3];
    const float* W2 = (const float*)d_in[4];
    const float* b2 = (const float*)d_in[5];
    const float* a  = (const float*)d_in[6];
    float* out = (float*)d_out;

    dim3 ggrid(F_DIM / GBN, (N_NODES + GBM - 1) / GBM);
    const int GAT = (N_NODES * 32 + 255) / 256;   // warp per node

    // ---- CSR build (shared by both layers) ----
    k_zero_counts<<<(N_NODES + 255) / 256, 256>>>();
    k_count<<<(NNZ + 255) / 256, 256>>>(ei);
    k_scan1<<<NB1, 1024>>>(0);
    k_scan1<<<NB1, 1024>>>(1);
    k_scan2<<<1, 128>>>(0);
    k_scan2<<<1, 128>>>(1);
    k_scan3<<<NB1, 1024>>>(0);
    k_scan3<<<NB1, 1024>>>(1);
    k_fill<<<(NNZ + 255) / 256, 256>>>(ei);

    // ---- layer 1 ----
    k_gemm<<<ggrid, 256>>>(x, W1, 0);
    k_gather_n2e<<<GAT, 256>>>();
    k_gather_e2n<<<GAT, 256>>>(out, b1, a, x, 0, 0);

    // ---- layer 2 ----
    k_gemm<<<ggrid, 256>>>(x /*unused*/, W2, 1);
    k_gather_n2e<<<GAT, 256>>>();
    k_gather_e2n<<<GAT, 256>>>(out, b2, a, x, 1, 1);
}